// round 1
// baseline (speedup 1.0000x reference)
#include <cuda_runtime.h>
#include <math.h>
#include <stdint.h>

// Problem constants (B=32, S=512, H=2048, FP=SP=1024)
#define NTOK 16384
#define HDIM 2048
#define CDIM 1024          // FP == SP == 1024
#define OUTW 2050          // 2 + FP + SP

// GEMM tiling
#define BM 128
#define BN 128
#define BK 16
#define KT (HDIM / BK)     // 128

// ---------------------------------------------------------------------------
// Scratch (allocation-free: __device__ globals)
// ---------------------------------------------------------------------------
__device__ float g_logits[2][(size_t)NTOK * CDIM];  // 134 MB: raw logits per class, by list position
__device__ int   g_list[2][NTOK];                   // compacted token indices per class
__device__ int   g_cnt[2];                          // per-class token counts
__device__ float g_nonend[NTOK];                    // 1 - sigmoid(end_logit)

// ---------------------------------------------------------------------------
// Kernel 0: reset counters (must run every graph replay)
// ---------------------------------------------------------------------------
__global__ void k_reset() {
    if (threadIdx.x < 2) g_cnt[threadIdx.x] = 0;
}

// ---------------------------------------------------------------------------
// Kernel 1: end head + classification + list build + exact zero-fill.
// One warp per token; 8 tokens per 256-thread block.
// ---------------------------------------------------------------------------
__global__ __launch_bounds__(256) void k_classify(
    const float* __restrict__ X, const int* __restrict__ pY,
    const float* __restrict__ W_end, const float* __restrict__ b_end,
    float* __restrict__ out)
{
    const int warp = threadIdx.x >> 5;
    const int lane = threadIdx.x & 31;
    const int t = blockIdx.x * 8 + warp;
    if (t >= NTOK) return;

    // end_logit = dot(X[t], W_end) + b_end
    const float4* x4 = reinterpret_cast<const float4*>(X + (size_t)t * HDIM);
    const float4* w4 = reinterpret_cast<const float4*>(W_end);
    float s = 0.f;
    #pragma unroll
    for (int i = 0; i < 16; ++i) {
        float4 a = x4[lane + 32 * i];
        float4 b = w4[lane + 32 * i];
        s += a.x * b.x + a.y * b.y + a.z * b.z + a.w * b.w;
    }
    #pragma unroll
    for (int o = 16; o; o >>= 1) s += __shfl_xor_sync(0xffffffffu, s, o);
    const float logit = s + b_end[0];
    const float p = 1.f / (1.f + expf(-logit));

    if (lane == 0) g_nonend[t] = 1.f - p;

    const int c = pY[t];
    float* lp  = out;                                   // [NTOK] log_prob
    float* row = out + NTOK + (size_t)t * OUTW;         // this token's prob_all row

    int z0, z1, z2, z3;  // two zero spans [z0,z1) U [z2,z3)
    if (c == 0) {
        if (lane == 0) { lp[t] = logf(p); row[0] = p; row[1] = p; }
        z0 = 2; z1 = OUTW; z2 = 0; z3 = 0;
    } else if (c == 1) {
        if (lane == 0) { int q = atomicAdd(&g_cnt[0], 1); g_list[0][q] = t; }
        z0 = 0; z1 = 2; z2 = 2 + CDIM; z3 = OUTW;
    } else if (c == 2) {
        if (lane == 0) { int q = atomicAdd(&g_cnt[1], 1); g_list[1][q] = t; }
        z0 = 0; z1 = 2 + CDIM; z2 = 0; z3 = 0;
    } else {
        if (lane == 0) lp[t] = 0.f;
        z0 = 0; z1 = OUTW; z2 = 0; z3 = 0;
    }
    for (int i = z0 + lane; i < z1; i += 32) row[i] = 0.f;
    for (int i = z2 + lane; i < z3; i += 32) row[i] = 0.f;
}

// ---------------------------------------------------------------------------
// Kernel 2: gathered-row SGEMM over compacted token lists.
// logits[pos, n] = X[list[pos], :] . W[n, :]   (bias added in softmax pass)
// 128x128 tile, BK=16, 256 threads, 8x8 micro-tile with packed f32x2 FMA.
// grid = (CDIM/BN, NTOK/BM, 2); CTAs past the class count exit.
// ---------------------------------------------------------------------------
__global__ __launch_bounds__(256) void k_gemm(
    const float* __restrict__ X,
    const float* __restrict__ W_hcw, const float* __restrict__ W_roo)
{
    const int z   = blockIdx.z;
    const int cnt = g_cnt[z];
    const int m0  = blockIdx.y * BM;
    if (m0 >= cnt) return;
    const int n0  = blockIdx.x * BN;
    const float* __restrict__ W = (z == 0) ? W_hcw : W_roo;
    float* __restrict__ Lg = g_logits[z];

    __shared__ __align__(16) float As[2][BK][BM + 4];
    __shared__ __align__(16) float Bs[2][BK][BN + 4];
    __shared__ int tok_s[BM];

    const int tid = threadIdx.x;
    if (tid < BM) {
        int m = m0 + tid;
        tok_s[tid] = g_list[z][(m < cnt) ? m : m0];  // clamp: safe dummy row
    }
    __syncthreads();

    // global-load mapping: each thread owns rows (tid>>2) and (tid>>2)+64,
    // K-chunk (tid&3)*4 .. +3 of each K-tile (float4 loads, coalesced).
    const int lrow = tid >> 2;
    const int lk   = (tid & 3) * 4;
    const float* Xp0 = X + (size_t)tok_s[lrow]      * HDIM + lk;
    const float* Xp1 = X + (size_t)tok_s[lrow + 64] * HDIM + lk;
    const float* Wp0 = W + (size_t)(n0 + lrow)      * HDIM + lk;
    const float* Wp1 = W + (size_t)(n0 + lrow + 64) * HDIM + lk;

    const int ty = tid >> 4;   // 0..15 -> rows ty*8..+7
    const int tx = tid & 15;   // 0..15 -> cols tx*8..+7

    // acc[i][jp] packs (row i, col 2jp) and (row i, col 2jp+1) as f32x2
    unsigned long long acc[8][4];
    #pragma unroll
    for (int i = 0; i < 8; ++i)
        #pragma unroll
        for (int j = 0; j < 4; ++j) acc[i][j] = 0ull;

    float4 a0, a1, b0, b1;

    // preload K-tile 0
    a0 = *reinterpret_cast<const float4*>(Xp0);
    a1 = *reinterpret_cast<const float4*>(Xp1);
    b0 = *reinterpret_cast<const float4*>(Wp0);
    b1 = *reinterpret_cast<const float4*>(Wp1);
    {
        As[0][lk+0][lrow] = a0.x; As[0][lk+1][lrow] = a0.y;
        As[0][lk+2][lrow] = a0.z; As[0][lk+3][lrow] = a0.w;
        As[0][lk+0][lrow+64] = a1.x; As[0][lk+1][lrow+64] = a1.y;
        As[0][lk+2][lrow+64] = a1.z; As[0][lk+3][lrow+64] = a1.w;
        Bs[0][lk+0][lrow] = b0.x; Bs[0][lk+1][lrow] = b0.y;
        Bs[0][lk+2][lrow] = b0.z; Bs[0][lk+3][lrow] = b0.w;
        Bs[0][lk+0][lrow+64] = b1.x; Bs[0][lk+1][lrow+64] = b1.y;
        Bs[0][lk+2][lrow+64] = b1.z; Bs[0][lk+3][lrow+64] = b1.w;
    }
    __syncthreads();

    for (int kt = 0; kt < KT; ++kt) {
        const int  cur = kt & 1;
        const bool nx  = (kt + 1) < KT;
        if (nx) {
            const int ko = (kt + 1) * BK;
            a0 = *reinterpret_cast<const float4*>(Xp0 + ko);
            a1 = *reinterpret_cast<const float4*>(Xp1 + ko);
            b0 = *reinterpret_cast<const float4*>(Wp0 + ko);
            b1 = *reinterpret_cast<const float4*>(Wp1 + ko);
        }
        #pragma unroll
        for (int k = 0; k < BK; ++k) {
            unsigned long long B2[4];
            #pragma unroll
            for (int jp = 0; jp < 4; ++jp)
                B2[jp] = *reinterpret_cast<const unsigned long long*>(
                             &Bs[cur][k][tx * 8 + 2 * jp]);
            #pragma unroll
            for (int i = 0; i < 8; ++i) {
                const unsigned int ai = __float_as_uint(As[cur][k][ty * 8 + i]);
                unsigned long long A2;
                asm("mov.b64 %0, {%1, %1};" : "=l"(A2) : "r"(ai));
                #pragma unroll
                for (int jp = 0; jp < 4; ++jp)
                    asm("fma.rn.f32x2 %0, %1, %2, %0;"
                        : "+l"(acc[i][jp]) : "l"(A2), "l"(B2[jp]));
            }
        }
        if (nx) {
            const int nb = cur ^ 1;
            As[nb][lk+0][lrow] = a0.x; As[nb][lk+1][lrow] = a0.y;
            As[nb][lk+2][lrow] = a0.z; As[nb][lk+3][lrow] = a0.w;
            As[nb][lk+0][lrow+64] = a1.x; As[nb][lk+1][lrow+64] = a1.y;
            As[nb][lk+2][lrow+64] = a1.z; As[nb][lk+3][lrow+64] = a1.w;
            Bs[nb][lk+0][lrow] = b0.x; Bs[nb][lk+1][lrow] = b0.y;
            Bs[nb][lk+2][lrow] = b0.z; Bs[nb][lk+3][lrow] = b0.w;
            Bs[nb][lk+0][lrow+64] = b1.x; Bs[nb][lk+1][lrow+64] = b1.y;
            Bs[nb][lk+2][lrow+64] = b1.z; Bs[nb][lk+3][lrow+64] = b1.w;
            __syncthreads();
        }
    }

    // epilogue: f32x2 accumulators store directly as 64-bit words
    #pragma unroll
    for (int i = 0; i < 8; ++i) {
        const int pos = m0 + ty * 8 + i;
        if (pos < cnt) {
            unsigned long long* dst = reinterpret_cast<unsigned long long*>(
                Lg + (size_t)pos * CDIM + n0 + tx * 8);
            #pragma unroll
            for (int jp = 0; jp < 4; ++jp) dst[jp] = acc[i][jp];
        }
    }
}

// ---------------------------------------------------------------------------
// Kernel 3: softmax + scale by non_end + scatter + log_prob gather.
// One warp per compacted token; 8 per block. grid = (NTOK/8, 1, 2).
// ---------------------------------------------------------------------------
__global__ __launch_bounds__(256) void k_softmax(
    const int* __restrict__ Y,
    const float* __restrict__ b_hcw, const float* __restrict__ b_roo,
    float* __restrict__ out)
{
    const int z    = blockIdx.z;
    const int warp = threadIdx.x >> 5;
    const int lane = threadIdx.x & 31;
    const int pos  = blockIdx.x * 8 + warp;
    if (pos >= g_cnt[z]) return;
    const int t = g_list[z][pos];

    const float* __restrict__ bias = (z == 0) ? b_hcw : b_roo;
    const float* Lrow = g_logits[z] + (size_t)pos * CDIM;
    const float4* L4 = reinterpret_cast<const float4*>(Lrow);
    const float4* B4 = reinterpret_cast<const float4*>(bias);

    float4 v[8];
    float mx = -1e30f;
    #pragma unroll
    for (int i = 0; i < 8; ++i) {
        float4 a = L4[lane + 32 * i];
        float4 b = B4[lane + 32 * i];
        a.x += b.x; a.y += b.y; a.z += b.z; a.w += b.w;
        v[i] = a;
        mx = fmaxf(mx, fmaxf(fmaxf(a.x, a.y), fmaxf(a.z, a.w)));
    }
    #pragma unroll
    for (int o = 16; o; o >>= 1) mx = fmaxf(mx, __shfl_xor_sync(0xffffffffu, mx, o));

    float sum = 0.f;
    #pragma unroll
    for (int i = 0; i < 8; ++i) {
        v[i].x = expf(v[i].x - mx); v[i].y = expf(v[i].y - mx);
        v[i].z = expf(v[i].z - mx); v[i].w = expf(v[i].w - mx);
        sum += (v[i].x + v[i].y) + (v[i].z + v[i].w);
    }
    #pragma unroll
    for (int o = 16; o; o >>= 1) sum += __shfl_xor_sync(0xffffffffu, sum, o);

    const float ne = g_nonend[t];
    const float scale = ne / sum;

    // scatter P * non_end into the class's column block (8-byte aligned)
    float* row = out + NTOK + (size_t)t * OUTW + ((z == 0) ? 2 : 2 + CDIM);
    #pragma unroll
    for (int i = 0; i < 8; ++i) {
        const int c0 = 4 * (lane + 32 * i);
        *reinterpret_cast<float2*>(row + c0)     = make_float2(v[i].x * scale, v[i].y * scale);
        *reinterpret_cast<float2*>(row + c0 + 2) = make_float2(v[i].z * scale, v[i].w * scale);
    }

    if (lane == 0) {
        const int yv  = Y[t];
        int idx = yv - 2 - ((z == 0) ? 0 : CDIM);
        idx = min(max(idx, 0), CDIM - 1);
        const float li = Lrow[idx] + bias[idx];
        // log(P[idx] * non_end) computed analytically for accuracy
        out[t] = (li - mx) - logf(sum) + logf(ne);
    }
}

// ---------------------------------------------------------------------------
// Launcher (graph-capturable: kernel launches only)
// ---------------------------------------------------------------------------
extern "C" void kernel_launch(void* const* d_in, const int* in_sizes, int n_in,
                              void* d_out, int out_size)
{
    const float* X     = (const float*)d_in[0];
    const int*   pY    = (const int*)d_in[1];
    const int*   Y     = (const int*)d_in[2];
    const float* W_end = (const float*)d_in[3];
    const float* b_end = (const float*)d_in[4];
    const float* W_hcw = (const float*)d_in[5];
    const float* b_hcw = (const float*)d_in[6];
    const float* W_roo = (const float*)d_in[7];
    const float* b_roo = (const float*)d_in[8];
    float* out = (float*)d_out;
    (void)in_sizes; (void)n_in; (void)out_size;

    k_reset<<<1, 32>>>();
    k_classify<<<NTOK / 8, 256>>>(X, pY, W_end, b_end, out);
    k_gemm<<<dim3(CDIM / BN, NTOK / BM, 2), 256>>>(X, W_hcw, W_roo);
    k_softmax<<<dim3(NTOK / 8, 1, 2), 256>>>(Y, b_hcw, b_roo, out);
}

// round 3
// speedup vs baseline: 2.4820x; 2.4820x over previous
#include <cuda_runtime.h>
#include <cuda_bf16.h>
#include <math.h>
#include <stdint.h>

// Problem constants (B=32, S=512, H=2048, FP=SP=1024)
#define NTOK 16384
#define HDIM 2048
#define CDIM 1024
#define OUTW 2050

// GEMM tiling (mma.sync path)
#define BM 128
#define BN 128
#define BK 64                  // bf16 elems per K-stage = 128 bytes/row
#define KT (HDIM / BK)         // 32
#define SPLIT_SZ 16384         // 128 rows x 128 bytes
#define STAGE_SZ (4 * SPLIT_SZ) // Ah, Al, Bh, Bl

// ---------------------------------------------------------------------------
// Scratch (allocation-free: __device__ globals)
// ---------------------------------------------------------------------------
__device__ float g_logits[2][(size_t)NTOK * CDIM];
__device__ __nv_bfloat16 g_Ahi[2][(size_t)NTOK * HDIM];
__device__ __nv_bfloat16 g_Alo[2][(size_t)NTOK * HDIM];
__device__ __nv_bfloat16 g_Whi[2][(size_t)CDIM * HDIM];
__device__ __nv_bfloat16 g_Wlo[2][(size_t)CDIM * HDIM];
__device__ int   g_list[2][NTOK];
__device__ int   g_cnt[2];
__device__ float g_nonend[NTOK];

// ---------------------------------------------------------------------------
// helpers
// ---------------------------------------------------------------------------
__device__ __forceinline__ uint32_t smem_u32(const void* p) {
    uint32_t a;
    asm("{ .reg .u64 t; cvta.to.shared.u64 t, %1; cvt.u32.u64 %0, t; }" : "=r"(a) : "l"(p));
    return a;
}
__device__ __forceinline__ uint32_t swz128(uint32_t o) { return o ^ ((o >> 3) & 0x70); }
__device__ __forceinline__ void cp16(uint32_t dst, const void* src) {
    asm volatile("cp.async.cg.shared.global [%0], [%1], 16;" :: "r"(dst), "l"(src));
}
__device__ __forceinline__ void cp_commit() { asm volatile("cp.async.commit_group;" ::: "memory"); }
template <int N> __device__ __forceinline__ void cp_wait() {
    asm volatile("cp.async.wait_group %0;" :: "n"(N) : "memory");
}
__device__ __forceinline__ void ldsm4(uint32_t* r, uint32_t addr) {
    asm volatile("ldmatrix.sync.aligned.m8n8.x4.shared.b16 {%0,%1,%2,%3}, [%4];"
                 : "=r"(r[0]), "=r"(r[1]), "=r"(r[2]), "=r"(r[3]) : "r"(addr));
}
__device__ __forceinline__ void hmma(float* c, const uint32_t* a, uint32_t b0, uint32_t b1) {
    asm volatile("mma.sync.aligned.m16n8k16.row.col.f32.bf16.bf16.f32 "
                 "{%0,%1,%2,%3}, {%4,%5,%6,%7}, {%8,%9}, {%0,%1,%2,%3};"
                 : "+f"(c[0]), "+f"(c[1]), "+f"(c[2]), "+f"(c[3])
                 : "r"(a[0]), "r"(a[1]), "r"(a[2]), "r"(a[3]), "r"(b0), "r"(b1));
}
__device__ __forceinline__ void split2(float a, float b, uint32_t& hi, uint32_t& lo) {
    __nv_bfloat162 h = __floats2bfloat162_rn(a, b);
    float2 hf = __bfloat1622float2(h);
    __nv_bfloat162 l = __floats2bfloat162_rn(a - hf.x, b - hf.y);
    hi = *reinterpret_cast<uint32_t*>(&h);
    lo = *reinterpret_cast<uint32_t*>(&l);
}

// ---------------------------------------------------------------------------
// Kernel 0: reset counters
// ---------------------------------------------------------------------------
__global__ void k_reset() {
    if (threadIdx.x < 2) g_cnt[threadIdx.x] = 0;
}

// ---------------------------------------------------------------------------
// Kernel 1: end head + classification + list build + exact zero-fill.
// ---------------------------------------------------------------------------
__global__ __launch_bounds__(256) void k_classify(
    const float* __restrict__ X, const int* __restrict__ pY,
    const float* __restrict__ W_end, const float* __restrict__ b_end,
    float* __restrict__ out)
{
    const int warp = threadIdx.x >> 5;
    const int lane = threadIdx.x & 31;
    const int t = blockIdx.x * 8 + warp;
    if (t >= NTOK) return;

    const float4* x4 = reinterpret_cast<const float4*>(X + (size_t)t * HDIM);
    const float4* w4 = reinterpret_cast<const float4*>(W_end);
    float s = 0.f;
    #pragma unroll
    for (int i = 0; i < 16; ++i) {
        float4 a = x4[lane + 32 * i];
        float4 b = w4[lane + 32 * i];
        s += a.x * b.x + a.y * b.y + a.z * b.z + a.w * b.w;
    }
    #pragma unroll
    for (int o = 16; o; o >>= 1) s += __shfl_xor_sync(0xffffffffu, s, o);
    const float logit = s + b_end[0];
    const float p = 1.f / (1.f + expf(-logit));

    if (lane == 0) g_nonend[t] = 1.f - p;

    const int c = pY[t];
    float* lp  = out;
    float* row = out + NTOK + (size_t)t * OUTW;

    int z0, z1, z2, z3;
    if (c == 0) {
        if (lane == 0) { lp[t] = logf(p); row[0] = p; row[1] = p; }
        z0 = 2; z1 = OUTW; z2 = 0; z3 = 0;
    } else if (c == 1) {
        if (lane == 0) { int q = atomicAdd(&g_cnt[0], 1); g_list[0][q] = t; }
        z0 = 0; z1 = 2; z2 = 2 + CDIM; z3 = OUTW;
    } else if (c == 2) {
        if (lane == 0) { int q = atomicAdd(&g_cnt[1], 1); g_list[1][q] = t; }
        z0 = 0; z1 = 2 + CDIM; z2 = 0; z3 = 0;
    } else {
        if (lane == 0) lp[t] = 0.f;
        z0 = 0; z1 = OUTW; z2 = 0; z3 = 0;
    }
    for (int i = z0 + lane; i < z1; i += 32) row[i] = 0.f;
    for (int i = z2 + lane; i < z3; i += 32) row[i] = 0.f;
}

// ---------------------------------------------------------------------------
// Kernel 2a: gather + split X rows into compacted bf16 hi/lo (padded to BM).
// ---------------------------------------------------------------------------
__global__ __launch_bounds__(256) void k_convert_x(const float* __restrict__ X)
{
    const int z = blockIdx.y;
    const int warp = threadIdx.x >> 5, lane = threadIdx.x & 31;
    const int pos = blockIdx.x * 8 + warp;
    const int cnt = g_cnt[z];
    const int pad = (cnt + BM - 1) & ~(BM - 1);
    if (pos >= pad) return;

    uint2* dh = reinterpret_cast<uint2*>(g_Ahi[z] + (size_t)pos * HDIM);
    uint2* dl = reinterpret_cast<uint2*>(g_Alo[z] + (size_t)pos * HDIM);
    if (pos < cnt) {
        const int t = g_list[z][pos];
        const float4* s = reinterpret_cast<const float4*>(X + (size_t)t * HDIM);
        #pragma unroll
        for (int i = 0; i < 16; ++i) {
            float4 v = s[lane + 32 * i];
            uint32_t h0, l0, h1, l1;
            split2(v.x, v.y, h0, l0);
            split2(v.z, v.w, h1, l1);
            dh[lane + 32 * i] = make_uint2(h0, h1);
            dl[lane + 32 * i] = make_uint2(l0, l1);
        }
    } else {
        #pragma unroll
        for (int i = 0; i < 16; ++i) {
            dh[lane + 32 * i] = make_uint2(0u, 0u);
            dl[lane + 32 * i] = make_uint2(0u, 0u);
        }
    }
}

// ---------------------------------------------------------------------------
// Kernel 2b: split weights into bf16 hi/lo.
// ---------------------------------------------------------------------------
__global__ __launch_bounds__(256) void k_convert_w(
    const float* __restrict__ W_hcw, const float* __restrict__ W_roo)
{
    const int z = blockIdx.y;
    const int warp = threadIdx.x >> 5, lane = threadIdx.x & 31;
    const int rowi = blockIdx.x * 8 + warp;
    if (rowi >= CDIM) return;
    const float* W = z ? W_roo : W_hcw;
    const float4* s = reinterpret_cast<const float4*>(W + (size_t)rowi * HDIM);
    uint2* dh = reinterpret_cast<uint2*>(g_Whi[z] + (size_t)rowi * HDIM);
    uint2* dl = reinterpret_cast<uint2*>(g_Wlo[z] + (size_t)rowi * HDIM);
    #pragma unroll
    for (int i = 0; i < 16; ++i) {
        float4 v = s[lane + 32 * i];
        uint32_t h0, l0, h1, l1;
        split2(v.x, v.y, h0, l0);
        split2(v.z, v.w, h1, l1);
        dh[lane + 32 * i] = make_uint2(h0, h1);
        dl[lane + 32 * i] = make_uint2(l0, l1);
    }
}

// ---------------------------------------------------------------------------
// Kernel 3: split-bf16 GEMM via mma.sync.m16n8k16 (HMMA).
// 128x128 CTA tile, BK=64, 2-stage cp.async, 8 warps (4M x 2N), warp 32x64.
// ---------------------------------------------------------------------------
__device__ __forceinline__ void load_stage(int z, int m0, int n0, int k0,
                                           uint32_t sbase, int tid)
{
    const __nv_bfloat16* Ah = g_Ahi[z];
    const __nv_bfloat16* Al = g_Alo[z];
    const __nv_bfloat16* Bh = g_Whi[z];
    const __nv_bfloat16* Bl = g_Wlo[z];
    #pragma unroll
    for (int i = 0; i < 4; ++i) {            // 1024 chunks per operand-half
        int c = tid + 256 * i;
        int r = c >> 3, cc = c & 7;
        uint32_t off = swz128((uint32_t)(r * 128 + cc * 16));
        size_t ga = (size_t)(m0 + r) * HDIM + k0 + cc * 8;
        size_t gb = (size_t)(n0 + r) * HDIM + k0 + cc * 8;
        cp16(sbase + off,                Ah + ga);
        cp16(sbase + SPLIT_SZ + off,     Al + ga);
        cp16(sbase + 2 * SPLIT_SZ + off, Bh + gb);
        cp16(sbase + 3 * SPLIT_SZ + off, Bl + gb);
    }
}

__global__ __launch_bounds__(256, 1) void k_gemm_mma()
{
    extern __shared__ char dsm[];
    const int z   = blockIdx.z;
    const int cnt = g_cnt[z];
    const int m0  = blockIdx.y * BM;
    if (m0 >= cnt) return;
    const int n0  = blockIdx.x * BN;
    const int tid  = threadIdx.x;
    const int wid  = tid >> 5;
    const int lane = tid & 31;
    const int warpM = wid & 3;      // 4 warps in M: rows warpM*32 .. +31
    const int warpN = wid >> 2;     // 2 warps in N: cols warpN*64 .. +63

    uint32_t sb = (smem_u32(dsm) + 127u) & ~127u;

    float acc[2][8][4];
    #pragma unroll
    for (int i = 0; i < 2; ++i)
        #pragma unroll
        for (int j = 0; j < 8; ++j)
            #pragma unroll
            for (int q = 0; q < 4; ++q) acc[i][j][q] = 0.f;

    load_stage(z, m0, n0, 0,  sb,            tid); cp_commit();
    load_stage(z, m0, n0, BK, sb + STAGE_SZ, tid); cp_commit();

    // per-lane ldmatrix address components
    const int sub  = lane >> 3;     // 0..3
    const int lrow = lane & 7;
    // A x4: rows (m + (sub&1)*8 + lrow), k-bytes +(sub>>1)*16
    const int a_row = warpM * 32 + (sub & 1) * 8 + lrow;
    const int a_kb  = (sub >> 1) * 16;
    // B x4: rows (n + (sub>>1)*8 + lrow), k-bytes +(sub&1)*16
    const int b_row = warpN * 64 + (sub >> 1) * 8 + lrow;
    const int b_kb  = (sub & 1) * 16;

    for (int kt = 0; kt < KT; ++kt) {
        if (kt == KT - 1) cp_wait<0>(); else cp_wait<1>();
        __syncthreads();
        const uint32_t st = sb + (kt & 1) * STAGE_SZ;

        #pragma unroll
        for (int s = 0; s < 4; ++s) {
            const int kb = s * 32;
            uint32_t Af[2][2][4];   // [split][mtile][4]
            uint32_t Bf[2][4][4];   // [split][n16 tile][4] -> n8 j: [j>>1][(j&1)*2+..]
            #pragma unroll
            for (int i = 0; i < 2; ++i) {
                uint32_t off = swz128((uint32_t)((a_row + i * 16) * 128 + kb + a_kb));
                ldsm4(Af[0][i], st + off);
                ldsm4(Af[1][i], st + SPLIT_SZ + off);
            }
            #pragma unroll
            for (int j = 0; j < 4; ++j) {
                uint32_t off = swz128((uint32_t)((b_row + j * 16) * 128 + kb + b_kb));
                ldsm4(Bf[0][j], st + 2 * SPLIT_SZ + off);
                ldsm4(Bf[1][j], st + 3 * SPLIT_SZ + off);
            }
            #pragma unroll
            for (int i = 0; i < 2; ++i)
                #pragma unroll
                for (int j = 0; j < 8; ++j) {
                    const uint32_t bh0 = Bf[0][j >> 1][(j & 1) * 2];
                    const uint32_t bh1 = Bf[0][j >> 1][(j & 1) * 2 + 1];
                    const uint32_t bl0 = Bf[1][j >> 1][(j & 1) * 2];
                    const uint32_t bl1 = Bf[1][j >> 1][(j & 1) * 2 + 1];
                    hmma(acc[i][j], Af[0][i], bh0, bh1);   // hi*hi
                    hmma(acc[i][j], Af[0][i], bl0, bl1);   // hi*lo
                    hmma(acc[i][j], Af[1][i], bh0, bh1);   // lo*hi
                }
        }
        __syncthreads();
        if (kt + 2 < KT) {
            load_stage(z, m0, n0, (kt + 2) * BK, st, tid);
            cp_commit();
        }
    }

    // epilogue: c-frag (m16n8): c0,c1 -> row g, cols 2t,2t+1; c2,c3 -> row g+8
    const int g = lane >> 2, tq = lane & 3;
    float* Lg = g_logits[z];
    #pragma unroll
    for (int i = 0; i < 2; ++i) {
        const int r0 = m0 + warpM * 32 + i * 16 + g;
        #pragma unroll
        for (int j = 0; j < 8; ++j) {
            const int col = n0 + warpN * 64 + j * 8 + 2 * tq;
            if (r0 < cnt)
                *reinterpret_cast<float2*>(Lg + (size_t)r0 * CDIM + col) =
                    make_float2(acc[i][j][0], acc[i][j][1]);
            if (r0 + 8 < cnt)
                *reinterpret_cast<float2*>(Lg + (size_t)(r0 + 8) * CDIM + col) =
                    make_float2(acc[i][j][2], acc[i][j][3]);
        }
    }
}

// ---------------------------------------------------------------------------
// Kernel 4: softmax + scale by non_end + scatter + log_prob.
// ---------------------------------------------------------------------------
__global__ __launch_bounds__(256) void k_softmax(
    const int* __restrict__ Y,
    const float* __restrict__ b_hcw, const float* __restrict__ b_roo,
    float* __restrict__ out)
{
    const int z    = blockIdx.z;
    const int warp = threadIdx.x >> 5;
    const int lane = threadIdx.x & 31;
    const int pos  = blockIdx.x * 8 + warp;
    if (pos >= g_cnt[z]) return;
    const int t = g_list[z][pos];

    const float* __restrict__ bias = (z == 0) ? b_hcw : b_roo;
    const float* Lrow = g_logits[z] + (size_t)pos * CDIM;
    const float4* L4 = reinterpret_cast<const float4*>(Lrow);
    const float4* B4 = reinterpret_cast<const float4*>(bias);

    float4 v[8];
    float mx = -1e30f;
    #pragma unroll
    for (int i = 0; i < 8; ++i) {
        float4 a = L4[lane + 32 * i];
        float4 b = B4[lane + 32 * i];
        a.x += b.x; a.y += b.y; a.z += b.z; a.w += b.w;
        v[i] = a;
        mx = fmaxf(mx, fmaxf(fmaxf(a.x, a.y), fmaxf(a.z, a.w)));
    }
    #pragma unroll
    for (int o = 16; o; o >>= 1) mx = fmaxf(mx, __shfl_xor_sync(0xffffffffu, mx, o));

    float sum = 0.f;
    #pragma unroll
    for (int i = 0; i < 8; ++i) {
        v[i].x = expf(v[i].x - mx); v[i].y = expf(v[i].y - mx);
        v[i].z = expf(v[i].z - mx); v[i].w = expf(v[i].w - mx);
        sum += (v[i].x + v[i].y) + (v[i].z + v[i].w);
    }
    #pragma unroll
    for (int o = 16; o; o >>= 1) sum += __shfl_xor_sync(0xffffffffu, sum, o);

    const float ne = g_nonend[t];
    const float scale = ne / sum;

    float* row = out + NTOK + (size_t)t * OUTW + ((z == 0) ? 2 : 2 + CDIM);
    #pragma unroll
    for (int i = 0; i < 8; ++i) {
        const int c0 = 4 * (lane + 32 * i);
        *reinterpret_cast<float2*>(row + c0)     = make_float2(v[i].x * scale, v[i].y * scale);
        *reinterpret_cast<float2*>(row + c0 + 2) = make_float2(v[i].z * scale, v[i].w * scale);
    }

    if (lane == 0) {
        const int yv = Y[t];
        int idx = yv - 2 - ((z == 0) ? 0 : CDIM);
        idx = min(max(idx, 0), CDIM - 1);
        const float li = Lrow[idx] + bias[idx];
        out[t] = (li - mx) - logf(sum) + logf(ne);
    }
}

// ---------------------------------------------------------------------------
// Launcher
// ---------------------------------------------------------------------------
extern "C" void kernel_launch(void* const* d_in, const int* in_sizes, int n_in,
                              void* d_out, int out_size)
{
    const float* X     = (const float*)d_in[0];
    const int*   pY    = (const int*)d_in[1];
    const int*   Y     = (const int*)d_in[2];
    const float* W_end = (const float*)d_in[3];
    const float* b_end = (const float*)d_in[4];
    const float* W_hcw = (const float*)d_in[5];
    const float* b_hcw = (const float*)d_in[6];
    const float* W_roo = (const float*)d_in[7];
    const float* b_roo = (const float*)d_in[8];
    float* out = (float*)d_out;
    (void)in_sizes; (void)n_in; (void)out_size;

    const int dyn = 128 + 2 * STAGE_SZ;   // 131200
    static bool attr_set = false;
    if (!attr_set) {
        cudaFuncSetAttribute(k_gemm_mma, cudaFuncAttributeMaxDynamicSharedMemorySize, dyn);
        attr_set = true;
    }

    k_reset<<<1, 32>>>();
    k_classify<<<NTOK / 8, 256>>>(X, pY, W_end, b_end, out);
    k_convert_x<<<dim3(NTOK / 8, 2), 256>>>(X);
    k_convert_w<<<dim3(CDIM / 8, 2), 256>>>(W_hcw, W_roo);
    k_gemm_mma<<<dim3(CDIM / BN, NTOK / BM, 2), 256, dyn>>>();
    k_softmax<<<dim3(NTOK / 8, 1, 2), 256>>>(Y, b_hcw, b_roo, out);
}

// round 4
// speedup vs baseline: 2.5194x; 1.0151x over previous
#include <cuda_runtime.h>
#include <cuda_bf16.h>
#include <math.h>
#include <stdint.h>

// Problem constants (B=32, S=512, H=2048, FP=SP=1024)
#define NTOK 16384
#define HDIM 2048
#define CDIM 1024
#define OUTW 2050

// GEMM tiling (mma.sync path)
#define BM 128
#define BN 128
#define BK 64                   // bf16 elems per K-stage = 128 bytes/row
#define KT (HDIM / BK)          // 32
#define SPLIT_SZ 16384          // 128 rows x 128 bytes
#define STAGE_SZ (4 * SPLIT_SZ) // Ah, Al, Bh, Bl = 64 KB
#define NSTAGE 3

// ---------------------------------------------------------------------------
// Scratch (allocation-free: __device__ globals)
// ---------------------------------------------------------------------------
__device__ float g_logits[2][(size_t)NTOK * CDIM];
__device__ __nv_bfloat16 g_Ahi[2][(size_t)NTOK * HDIM];
__device__ __nv_bfloat16 g_Alo[2][(size_t)NTOK * HDIM];
__device__ __nv_bfloat16 g_Whi[2][(size_t)CDIM * HDIM];
__device__ __nv_bfloat16 g_Wlo[2][(size_t)CDIM * HDIM];
__device__ int   g_list[2][NTOK];
__device__ int   g_cnt[2];
__device__ float g_nonend[NTOK];

// ---------------------------------------------------------------------------
// helpers
// ---------------------------------------------------------------------------
__device__ __forceinline__ uint32_t smem_u32(const void* p) {
    uint32_t a;
    asm("{ .reg .u64 t; cvta.to.shared.u64 t, %1; cvt.u32.u64 %0, t; }" : "=r"(a) : "l"(p));
    return a;
}
__device__ __forceinline__ uint32_t swz128(uint32_t o) { return o ^ ((o >> 3) & 0x70); }
__device__ __forceinline__ void cp16(uint32_t dst, const void* src) {
    asm volatile("cp.async.cg.shared.global [%0], [%1], 16;" :: "r"(dst), "l"(src));
}
__device__ __forceinline__ void cp_commit() { asm volatile("cp.async.commit_group;" ::: "memory"); }
template <int N> __device__ __forceinline__ void cp_wait() {
    asm volatile("cp.async.wait_group %0;" :: "n"(N) : "memory");
}
__device__ __forceinline__ void ldsm4(uint32_t* r, uint32_t addr) {
    asm volatile("ldmatrix.sync.aligned.m8n8.x4.shared.b16 {%0,%1,%2,%3}, [%4];"
                 : "=r"(r[0]), "=r"(r[1]), "=r"(r[2]), "=r"(r[3]) : "r"(addr));
}
__device__ __forceinline__ void hmma(float* c, const uint32_t* a, uint32_t b0, uint32_t b1) {
    asm volatile("mma.sync.aligned.m16n8k16.row.col.f32.bf16.bf16.f32 "
                 "{%0,%1,%2,%3}, {%4,%5,%6,%7}, {%8,%9}, {%0,%1,%2,%3};"
                 : "+f"(c[0]), "+f"(c[1]), "+f"(c[2]), "+f"(c[3])
                 : "r"(a[0]), "r"(a[1]), "r"(a[2]), "r"(a[3]), "r"(b0), "r"(b1));
}
__device__ __forceinline__ void split2(float a, float b, uint32_t& hi, uint32_t& lo) {
    __nv_bfloat162 h = __floats2bfloat162_rn(a, b);
    float2 hf = __bfloat1622float2(h);
    __nv_bfloat162 l = __floats2bfloat162_rn(a - hf.x, b - hf.y);
    hi = *reinterpret_cast<uint32_t*>(&h);
    lo = *reinterpret_cast<uint32_t*>(&l);
}

// ---------------------------------------------------------------------------
// Kernel 0: reset counters
// ---------------------------------------------------------------------------
__global__ void k_reset() {
    if (threadIdx.x < 2) g_cnt[threadIdx.x] = 0;
}

// ---------------------------------------------------------------------------
// Kernel 1: end head + classification + list build + zero-fill + FUSED X-split.
// The warp that owns token t also writes its bf16 hi/lo row at compacted pos q.
// ---------------------------------------------------------------------------
__global__ __launch_bounds__(256) void k_classify(
    const float* __restrict__ X, const int* __restrict__ pY,
    const float* __restrict__ W_end, const float* __restrict__ b_end,
    float* __restrict__ out)
{
    const int warp = threadIdx.x >> 5;
    const int lane = threadIdx.x & 31;
    const int t = blockIdx.x * 8 + warp;
    if (t >= NTOK) return;

    const float4* x4 = reinterpret_cast<const float4*>(X + (size_t)t * HDIM);
    const float4* w4 = reinterpret_cast<const float4*>(W_end);
    float s = 0.f;
    #pragma unroll
    for (int i = 0; i < 16; ++i) {
        float4 a = x4[lane + 32 * i];
        float4 b = w4[lane + 32 * i];
        s += a.x * b.x + a.y * b.y + a.z * b.z + a.w * b.w;
    }
    #pragma unroll
    for (int o = 16; o; o >>= 1) s += __shfl_xor_sync(0xffffffffu, s, o);
    const float logit = s + b_end[0];
    const float p = 1.f / (1.f + expf(-logit));

    if (lane == 0) g_nonend[t] = 1.f - p;

    const int c = pY[t];
    float* lp  = out;
    float* row = out + NTOK + (size_t)t * OUTW;

    int z0, z1, z2, z3;
    if (c == 0) {
        if (lane == 0) { lp[t] = logf(p); row[0] = p; row[1] = p; }
        z0 = 2; z1 = OUTW; z2 = 0; z3 = 0;
    } else if (c == 1 || c == 2) {
        const int z = c - 1;
        int q = 0;
        if (lane == 0) { q = atomicAdd(&g_cnt[z], 1); g_list[z][q] = t; }
        q = __shfl_sync(0xffffffffu, q, 0);
        // fused split write: X row -> g_Ahi[z][q], g_Alo[z][q] (rows hot in L1)
        uint2* dh = reinterpret_cast<uint2*>(g_Ahi[z] + (size_t)q * HDIM);
        uint2* dl = reinterpret_cast<uint2*>(g_Alo[z] + (size_t)q * HDIM);
        #pragma unroll
        for (int i = 0; i < 16; ++i) {
            float4 v = x4[lane + 32 * i];
            uint32_t h0, l0, h1, l1;
            split2(v.x, v.y, h0, l0);
            split2(v.z, v.w, h1, l1);
            dh[lane + 32 * i] = make_uint2(h0, h1);
            dl[lane + 32 * i] = make_uint2(l0, l1);
        }
        if (z == 0) { z0 = 0; z1 = 2; z2 = 2 + CDIM; z3 = OUTW; }
        else        { z0 = 0; z1 = 2 + CDIM; z2 = 0; z3 = 0; }
    } else {
        if (lane == 0) lp[t] = 0.f;
        z0 = 0; z1 = OUTW; z2 = 0; z3 = 0;
    }
    for (int i = z0 + lane; i < z1; i += 32) row[i] = 0.f;
    for (int i = z2 + lane; i < z3; i += 32) row[i] = 0.f;
}

// ---------------------------------------------------------------------------
// Kernel 1b: zero the A pad rows [cnt, ceil128(cnt)) per class.
// grid (16, 2), 256 thr: block b zeroes candidate rows cnt + b*8 + warp.
// ---------------------------------------------------------------------------
__global__ __launch_bounds__(256) void k_padzero()
{
    const int z = blockIdx.y;
    const int cnt = g_cnt[z];
    const int pad = (cnt + BM - 1) & ~(BM - 1);
    const int warp = threadIdx.x >> 5, lane = threadIdx.x & 31;
    const int pos = cnt + blockIdx.x * 8 + warp;
    if (pos >= pad) return;
    uint2* dh = reinterpret_cast<uint2*>(g_Ahi[z] + (size_t)pos * HDIM);
    uint2* dl = reinterpret_cast<uint2*>(g_Alo[z] + (size_t)pos * HDIM);
    #pragma unroll
    for (int i = 0; i < 16; ++i) {
        dh[lane + 32 * i] = make_uint2(0u, 0u);
        dl[lane + 32 * i] = make_uint2(0u, 0u);
    }
}

// ---------------------------------------------------------------------------
// Kernel 2: split weights into bf16 hi/lo. Half-row per warp.
// ---------------------------------------------------------------------------
__global__ __launch_bounds__(256) void k_convert_w(
    const float* __restrict__ W_hcw, const float* __restrict__ W_roo)
{
    const int z = blockIdx.y;
    const int warp = threadIdx.x >> 5, lane = threadIdx.x & 31;
    const int half = blockIdx.x * 8 + warp;        // 0 .. 2*CDIM-1
    if (half >= 2 * CDIM) return;
    const int rowi = half >> 1;
    const int off  = (half & 1) * 256;             // float4 offset within row
    const float* W = z ? W_roo : W_hcw;
    const float4* s = reinterpret_cast<const float4*>(W + (size_t)rowi * HDIM) + off;
    uint2* dh = reinterpret_cast<uint2*>(g_Whi[z] + (size_t)rowi * HDIM) + off;
    uint2* dl = reinterpret_cast<uint2*>(g_Wlo[z] + (size_t)rowi * HDIM) + off;
    #pragma unroll
    for (int i = 0; i < 8; ++i) {
        float4 v = s[lane + 32 * i];
        uint32_t h0, l0, h1, l1;
        split2(v.x, v.y, h0, l0);
        split2(v.z, v.w, h1, l1);
        dh[lane + 32 * i] = make_uint2(h0, h1);
        dl[lane + 32 * i] = make_uint2(l0, l1);
    }
}

// ---------------------------------------------------------------------------
// Kernel 3: split-bf16 GEMM via mma.sync.m16n8k16 (HMMA).
// 128x128 CTA tile, BK=64, 3-stage cp.async pipeline, single sync per K-iter.
// 8 warps (4M x 2N), warp tile 32x64.
// ---------------------------------------------------------------------------
__device__ __forceinline__ void load_stage(int z, int m0, int n0, int k0,
                                           uint32_t sbase, int tid)
{
    const __nv_bfloat16* Ah = g_Ahi[z];
    const __nv_bfloat16* Al = g_Alo[z];
    const __nv_bfloat16* Bh = g_Whi[z];
    const __nv_bfloat16* Bl = g_Wlo[z];
    #pragma unroll
    for (int i = 0; i < 4; ++i) {
        int c = tid + 256 * i;
        int r = c >> 3, cc = c & 7;
        uint32_t off = swz128((uint32_t)(r * 128 + cc * 16));
        size_t ga = (size_t)(m0 + r) * HDIM + k0 + cc * 8;
        size_t gb = (size_t)(n0 + r) * HDIM + k0 + cc * 8;
        cp16(sbase + off,                Ah + ga);
        cp16(sbase + SPLIT_SZ + off,     Al + ga);
        cp16(sbase + 2 * SPLIT_SZ + off, Bh + gb);
        cp16(sbase + 3 * SPLIT_SZ + off, Bl + gb);
    }
}

__global__ __launch_bounds__(256, 1) void k_gemm_mma()
{
    extern __shared__ char dsm[];
    const int z   = blockIdx.z;
    const int cnt = g_cnt[z];
    const int m0  = blockIdx.y * BM;
    if (m0 >= cnt) return;
    const int n0  = blockIdx.x * BN;
    const int tid  = threadIdx.x;
    const int wid  = tid >> 5;
    const int lane = tid & 31;
    const int warpM = wid & 3;
    const int warpN = wid >> 2;

    uint32_t sb = (smem_u32(dsm) + 127u) & ~127u;

    float acc[2][8][4];
    #pragma unroll
    for (int i = 0; i < 2; ++i)
        #pragma unroll
        for (int j = 0; j < 8; ++j)
            #pragma unroll
            for (int q = 0; q < 4; ++q) acc[i][j][q] = 0.f;

    // prologue: stages 0 and 1 in flight
    load_stage(z, m0, n0, 0,  sb,            tid); cp_commit();
    load_stage(z, m0, n0, BK, sb + STAGE_SZ, tid); cp_commit();

    const int sub  = lane >> 3;
    const int lrow = lane & 7;
    const int a_row = warpM * 32 + (sub & 1) * 8 + lrow;
    const int a_kb  = (sub >> 1) * 16;
    const int b_row = warpN * 64 + (sub >> 1) * 8 + lrow;
    const int b_kb  = (sub & 1) * 16;

    for (int kt = 0; kt < KT; ++kt) {
        if (kt >= KT - 1) cp_wait<0>(); else cp_wait<1>();
        __syncthreads();   // stage kt ready; buffer (kt-1)%3 free for reuse
        if (kt + 2 < KT) {
            load_stage(z, m0, n0, (kt + 2) * BK, sb + ((kt + 2) % NSTAGE) * STAGE_SZ, tid);
            cp_commit();
        }
        const uint32_t st = sb + (kt % NSTAGE) * STAGE_SZ;

        #pragma unroll
        for (int s = 0; s < 4; ++s) {
            const int kb = s * 32;
            uint32_t Af[2][2][4];
            uint32_t Bf[2][4][4];
            #pragma unroll
            for (int i = 0; i < 2; ++i) {
                uint32_t off = swz128((uint32_t)((a_row + i * 16) * 128 + kb + a_kb));
                ldsm4(Af[0][i], st + off);
                ldsm4(Af[1][i], st + SPLIT_SZ + off);
            }
            #pragma unroll
            for (int j = 0; j < 4; ++j) {
                uint32_t off = swz128((uint32_t)((b_row + j * 16) * 128 + kb + b_kb));
                ldsm4(Bf[0][j], st + 2 * SPLIT_SZ + off);
                ldsm4(Bf[1][j], st + 3 * SPLIT_SZ + off);
            }
            #pragma unroll
            for (int i = 0; i < 2; ++i)
                #pragma unroll
                for (int j = 0; j < 8; ++j) {
                    const uint32_t bh0 = Bf[0][j >> 1][(j & 1) * 2];
                    const uint32_t bh1 = Bf[0][j >> 1][(j & 1) * 2 + 1];
                    const uint32_t bl0 = Bf[1][j >> 1][(j & 1) * 2];
                    const uint32_t bl1 = Bf[1][j >> 1][(j & 1) * 2 + 1];
                    hmma(acc[i][j], Af[0][i], bh0, bh1);   // hi*hi
                    hmma(acc[i][j], Af[0][i], bl0, bl1);   // hi*lo
                    hmma(acc[i][j], Af[1][i], bh0, bh1);   // lo*hi
                }
        }
    }

    const int g = lane >> 2, tq = lane & 3;
    float* Lg = g_logits[z];
    #pragma unroll
    for (int i = 0; i < 2; ++i) {
        const int r0 = m0 + warpM * 32 + i * 16 + g;
        #pragma unroll
        for (int j = 0; j < 8; ++j) {
            const int col = n0 + warpN * 64 + j * 8 + 2 * tq;
            if (r0 < cnt)
                *reinterpret_cast<float2*>(Lg + (size_t)r0 * CDIM + col) =
                    make_float2(acc[i][j][0], acc[i][j][1]);
            if (r0 + 8 < cnt)
                *reinterpret_cast<float2*>(Lg + (size_t)(r0 + 8) * CDIM + col) =
                    make_float2(acc[i][j][2], acc[i][j][3]);
        }
    }
}

// ---------------------------------------------------------------------------
// Kernel 4: softmax + scale by non_end + scatter + log_prob.
// ---------------------------------------------------------------------------
__global__ __launch_bounds__(256) void k_softmax(
    const int* __restrict__ Y,
    const float* __restrict__ b_hcw, const float* __restrict__ b_roo,
    float* __restrict__ out)
{
    const int z    = blockIdx.z;
    const int warp = threadIdx.x >> 5;
    const int lane = threadIdx.x & 31;
    const int pos  = blockIdx.x * 8 + warp;
    if (pos >= g_cnt[z]) return;
    const int t = g_list[z][pos];

    const float* __restrict__ bias = (z == 0) ? b_hcw : b_roo;
    const float* Lrow = g_logits[z] + (size_t)pos * CDIM;
    const float4* L4 = reinterpret_cast<const float4*>(Lrow);
    const float4* B4 = reinterpret_cast<const float4*>(bias);

    float4 v[8];
    float mx = -1e30f;
    #pragma unroll
    for (int i = 0; i < 8; ++i) {
        float4 a = L4[lane + 32 * i];
        float4 b = B4[lane + 32 * i];
        a.x += b.x; a.y += b.y; a.z += b.z; a.w += b.w;
        v[i] = a;
        mx = fmaxf(mx, fmaxf(fmaxf(a.x, a.y), fmaxf(a.z, a.w)));
    }
    #pragma unroll
    for (int o = 16; o; o >>= 1) mx = fmaxf(mx, __shfl_xor_sync(0xffffffffu, mx, o));

    float sum = 0.f;
    #pragma unroll
    for (int i = 0; i < 8; ++i) {
        v[i].x = expf(v[i].x - mx); v[i].y = expf(v[i].y - mx);
        v[i].z = expf(v[i].z - mx); v[i].w = expf(v[i].w - mx);
        sum += (v[i].x + v[i].y) + (v[i].z + v[i].w);
    }
    #pragma unroll
    for (int o = 16; o; o >>= 1) sum += __shfl_xor_sync(0xffffffffu, sum, o);

    const float ne = g_nonend[t];
    const float scale = ne / sum;

    float* row = out + NTOK + (size_t)t * OUTW + ((z == 0) ? 2 : 2 + CDIM);
    #pragma unroll
    for (int i = 0; i < 8; ++i) {
        const int c0 = 4 * (lane + 32 * i);
        *reinterpret_cast<float2*>(row + c0)     = make_float2(v[i].x * scale, v[i].y * scale);
        *reinterpret_cast<float2*>(row + c0 + 2) = make_float2(v[i].z * scale, v[i].w * scale);
    }

    if (lane == 0) {
        const int yv = Y[t];
        int idx = yv - 2 - ((z == 0) ? 0 : CDIM);
        idx = min(max(idx, 0), CDIM - 1);
        const float li = Lrow[idx] + bias[idx];
        out[t] = (li - mx) - logf(sum) + logf(ne);
    }
}

// ---------------------------------------------------------------------------
// Launcher
// ---------------------------------------------------------------------------
extern "C" void kernel_launch(void* const* d_in, const int* in_sizes, int n_in,
                              void* d_out, int out_size)
{
    const float* X     = (const float*)d_in[0];
    const int*   pY    = (const int*)d_in[1];
    const int*   Y     = (const int*)d_in[2];
    const float* W_end = (const float*)d_in[3];
    const float* b_end = (const float*)d_in[4];
    const float* W_hcw = (const float*)d_in[5];
    const float* b_hcw = (const float*)d_in[6];
    const float* W_roo = (const float*)d_in[7];
    const float* b_roo = (const float*)d_in[8];
    float* out = (float*)d_out;
    (void)in_sizes; (void)n_in; (void)out_size;

    const int dyn = 128 + NSTAGE * STAGE_SZ;   // 196736
    static bool attr_set = false;
    if (!attr_set) {
        cudaFuncSetAttribute(k_gemm_mma, cudaFuncAttributeMaxDynamicSharedMemorySize, dyn);
        attr_set = true;
    }

    k_reset<<<1, 32>>>();
    k_classify<<<NTOK / 8, 256>>>(X, pY, W_end, b_end, out);
    k_padzero<<<dim3(16, 2), 256>>>();
    k_convert_w<<<dim3(2 * CDIM / 8, 2), 256>>>(W_hcw, W_roo);
    k_gemm_mma<<<dim3(CDIM / BN, NTOK / BM, 2), 256, dyn>>>();
    k_softmax<<<dim3(NTOK / 8, 1, 2), 256>>>(Y, b_hcw, b_roo, out);
}

// round 5
// speedup vs baseline: 2.5521x; 1.0130x over previous
#include <cuda_runtime.h>
#include <cuda_bf16.h>
#include <math.h>
#include <stdint.h>

// Problem constants (B=32, S=512, H=2048, FP=SP=1024)
#define NTOK 16384
#define HDIM 2048
#define CDIM 1024
#define OUTW 2050

// GEMM tiling (mma.sync path)
#define BM 128
#define BN 128
#define BK 64                   // bf16 elems per K-stage = 128 bytes/row
#define KT (HDIM / BK)          // 32
#define SPLIT_SZ 16384          // 128 rows x 128 bytes
#define STAGE_SZ (4 * SPLIT_SZ) // Ah, Al, Bh, Bl = 64 KB
#define NSTAGE 3

// ---------------------------------------------------------------------------
// Scratch (allocation-free: __device__ globals)
// ---------------------------------------------------------------------------
__device__ float g_logits[2][(size_t)NTOK * CDIM];
__device__ __nv_bfloat16 g_Ahi[2][(size_t)NTOK * HDIM];
__device__ __nv_bfloat16 g_Alo[2][(size_t)NTOK * HDIM];
__device__ __nv_bfloat16 g_Whi[2][(size_t)CDIM * HDIM];
__device__ __nv_bfloat16 g_Wlo[2][(size_t)CDIM * HDIM];
__device__ int   g_list[2][NTOK];
__device__ int   g_cnt[2];
__device__ float g_nonend[NTOK];

// ---------------------------------------------------------------------------
// helpers
// ---------------------------------------------------------------------------
__device__ __forceinline__ uint32_t smem_u32(const void* p) {
    uint32_t a;
    asm("{ .reg .u64 t; cvta.to.shared.u64 t, %1; cvt.u32.u64 %0, t; }" : "=r"(a) : "l"(p));
    return a;
}
__device__ __forceinline__ uint32_t swz128(uint32_t o) { return o ^ ((o >> 3) & 0x70); }
__device__ __forceinline__ void cp16(uint32_t dst, const void* src) {
    asm volatile("cp.async.cg.shared.global [%0], [%1], 16;" :: "r"(dst), "l"(src));
}
__device__ __forceinline__ void cp_commit() { asm volatile("cp.async.commit_group;" ::: "memory"); }
template <int N> __device__ __forceinline__ void cp_wait() {
    asm volatile("cp.async.wait_group %0;" :: "n"(N) : "memory");
}
__device__ __forceinline__ void ldsm4(uint32_t* r, uint32_t addr) {
    asm volatile("ldmatrix.sync.aligned.m8n8.x4.shared.b16 {%0,%1,%2,%3}, [%4];"
                 : "=r"(r[0]), "=r"(r[1]), "=r"(r[2]), "=r"(r[3]) : "r"(addr));
}
__device__ __forceinline__ void hmma(float* c, const uint32_t* a, uint32_t b0, uint32_t b1) {
    asm volatile("mma.sync.aligned.m16n8k16.row.col.f32.bf16.bf16.f32 "
                 "{%0,%1,%2,%3}, {%4,%5,%6,%7}, {%8,%9}, {%0,%1,%2,%3};"
                 : "+f"(c[0]), "+f"(c[1]), "+f"(c[2]), "+f"(c[3])
                 : "r"(a[0]), "r"(a[1]), "r"(a[2]), "r"(a[3]), "r"(b0), "r"(b1));
}
__device__ __forceinline__ void split2(float a, float b, uint32_t& hi, uint32_t& lo) {
    __nv_bfloat162 h = __floats2bfloat162_rn(a, b);
    float2 hf = __bfloat1622float2(h);
    __nv_bfloat162 l = __floats2bfloat162_rn(a - hf.x, b - hf.y);
    hi = *reinterpret_cast<uint32_t*>(&h);
    lo = *reinterpret_cast<uint32_t*>(&l);
}

// ---------------------------------------------------------------------------
// Kernel 0: reset counters
// ---------------------------------------------------------------------------
__global__ void k_reset() {
    if (threadIdx.x < 2) g_cnt[threadIdx.x] = 0;
}

// ---------------------------------------------------------------------------
// Kernel 1: end head + classification + list build + zero-fill + FUSED X-split.
// ---------------------------------------------------------------------------
__global__ __launch_bounds__(256) void k_classify(
    const float* __restrict__ X, const int* __restrict__ pY,
    const float* __restrict__ W_end, const float* __restrict__ b_end,
    float* __restrict__ out)
{
    const int warp = threadIdx.x >> 5;
    const int lane = threadIdx.x & 31;
    const int t = blockIdx.x * 8 + warp;
    if (t >= NTOK) return;

    const float4* x4 = reinterpret_cast<const float4*>(X + (size_t)t * HDIM);
    const float4* w4 = reinterpret_cast<const float4*>(W_end);
    float s = 0.f;
    #pragma unroll
    for (int i = 0; i < 16; ++i) {
        float4 a = x4[lane + 32 * i];
        float4 b = w4[lane + 32 * i];
        s += a.x * b.x + a.y * b.y + a.z * b.z + a.w * b.w;
    }
    #pragma unroll
    for (int o = 16; o; o >>= 1) s += __shfl_xor_sync(0xffffffffu, s, o);
    const float logit = s + b_end[0];
    const float p = 1.f / (1.f + expf(-logit));

    if (lane == 0) g_nonend[t] = 1.f - p;

    const int c = pY[t];
    float* lp  = out;
    float* row = out + NTOK + (size_t)t * OUTW;

    int z0, z1, z2, z3;
    if (c == 0) {
        if (lane == 0) { lp[t] = logf(p); row[0] = p; row[1] = p; }
        z0 = 2; z1 = OUTW; z2 = 0; z3 = 0;
    } else if (c == 1 || c == 2) {
        const int z = c - 1;
        int q = 0;
        if (lane == 0) { q = atomicAdd(&g_cnt[z], 1); g_list[z][q] = t; }
        q = __shfl_sync(0xffffffffu, q, 0);
        uint2* dh = reinterpret_cast<uint2*>(g_Ahi[z] + (size_t)q * HDIM);
        uint2* dl = reinterpret_cast<uint2*>(g_Alo[z] + (size_t)q * HDIM);
        #pragma unroll
        for (int i = 0; i < 16; ++i) {
            float4 v = x4[lane + 32 * i];
            uint32_t h0, l0, h1, l1;
            split2(v.x, v.y, h0, l0);
            split2(v.z, v.w, h1, l1);
            dh[lane + 32 * i] = make_uint2(h0, h1);
            dl[lane + 32 * i] = make_uint2(l0, l1);
        }
        if (z == 0) { z0 = 0; z1 = 2; z2 = 2 + CDIM; z3 = OUTW; }
        else        { z0 = 0; z1 = 2 + CDIM; z2 = 0; z3 = 0; }
    } else {
        if (lane == 0) lp[t] = 0.f;
        z0 = 0; z1 = OUTW; z2 = 0; z3 = 0;
    }
    for (int i = z0 + lane; i < z1; i += 32) row[i] = 0.f;
    for (int i = z2 + lane; i < z3; i += 32) row[i] = 0.f;
}

// ---------------------------------------------------------------------------
// Kernel 1b: zero the A pad rows [cnt, ceil128(cnt)) per class.
// ---------------------------------------------------------------------------
__global__ __launch_bounds__(256) void k_padzero()
{
    const int z = blockIdx.y;
    const int cnt = g_cnt[z];
    const int pad = (cnt + BM - 1) & ~(BM - 1);
    const int warp = threadIdx.x >> 5, lane = threadIdx.x & 31;
    const int pos = cnt + blockIdx.x * 8 + warp;
    if (pos >= pad) return;
    uint2* dh = reinterpret_cast<uint2*>(g_Ahi[z] + (size_t)pos * HDIM);
    uint2* dl = reinterpret_cast<uint2*>(g_Alo[z] + (size_t)pos * HDIM);
    #pragma unroll
    for (int i = 0; i < 16; ++i) {
        dh[lane + 32 * i] = make_uint2(0u, 0u);
        dl[lane + 32 * i] = make_uint2(0u, 0u);
    }
}

// ---------------------------------------------------------------------------
// Kernel 2: split weights into bf16 hi/lo. Half-row per warp.
// ---------------------------------------------------------------------------
__global__ __launch_bounds__(256) void k_convert_w(
    const float* __restrict__ W_hcw, const float* __restrict__ W_roo)
{
    const int z = blockIdx.y;
    const int warp = threadIdx.x >> 5, lane = threadIdx.x & 31;
    const int half = blockIdx.x * 8 + warp;
    if (half >= 2 * CDIM) return;
    const int rowi = half >> 1;
    const int off  = (half & 1) * 256;
    const float* W = z ? W_roo : W_hcw;
    const float4* s = reinterpret_cast<const float4*>(W + (size_t)rowi * HDIM) + off;
    uint2* dh = reinterpret_cast<uint2*>(g_Whi[z] + (size_t)rowi * HDIM) + off;
    uint2* dl = reinterpret_cast<uint2*>(g_Wlo[z] + (size_t)rowi * HDIM) + off;
    #pragma unroll
    for (int i = 0; i < 8; ++i) {
        float4 v = s[lane + 32 * i];
        uint32_t h0, l0, h1, l1;
        split2(v.x, v.y, h0, l0);
        split2(v.z, v.w, h1, l1);
        dh[lane + 32 * i] = make_uint2(h0, h1);
        dl[lane + 32 * i] = make_uint2(l0, l1);
    }
}

// ---------------------------------------------------------------------------
// Kernel 3: split-bf16 GEMM via mma.sync.m16n8k16 (HMMA).
// 128x128 CTA tile, BK=64, 3-stage cp.async pipeline, single sync per K-iter,
// EXPLICIT fragment double-buffering across s-steps (LDSM s+1 overlaps MMA s).
// ---------------------------------------------------------------------------
__device__ __forceinline__ void load_stage(int z, int m0, int n0, int k0,
                                           uint32_t sbase, int tid)
{
    const __nv_bfloat16* Ah = g_Ahi[z];
    const __nv_bfloat16* Al = g_Alo[z];
    const __nv_bfloat16* Bh = g_Whi[z];
    const __nv_bfloat16* Bl = g_Wlo[z];
    #pragma unroll
    for (int i = 0; i < 4; ++i) {
        int c = tid + 256 * i;
        int r = c >> 3, cc = c & 7;
        uint32_t off = swz128((uint32_t)(r * 128 + cc * 16));
        size_t ga = (size_t)(m0 + r) * HDIM + k0 + cc * 8;
        size_t gb = (size_t)(n0 + r) * HDIM + k0 + cc * 8;
        cp16(sbase + off,                Ah + ga);
        cp16(sbase + SPLIT_SZ + off,     Al + ga);
        cp16(sbase + 2 * SPLIT_SZ + off, Bh + gb);
        cp16(sbase + 3 * SPLIT_SZ + off, Bl + gb);
    }
}

// load all 12 ldsm4 frags for one k16 step (kb = byte offset of k within stage)
__device__ __forceinline__ void load_frags(
    uint32_t Af[2][2][4], uint32_t Bf[2][4][4], uint32_t st, int kb,
    int a_row, int a_kb, int b_row, int b_kb)
{
    #pragma unroll
    for (int i = 0; i < 2; ++i) {
        uint32_t off = swz128((uint32_t)((a_row + i * 16) * 128 + kb + a_kb));
        ldsm4(Af[0][i], st + off);
        ldsm4(Af[1][i], st + SPLIT_SZ + off);
    }
    #pragma unroll
    for (int j = 0; j < 4; ++j) {
        uint32_t off = swz128((uint32_t)((b_row + j * 16) * 128 + kb + b_kb));
        ldsm4(Bf[0][j], st + 2 * SPLIT_SZ + off);
        ldsm4(Bf[1][j], st + 3 * SPLIT_SZ + off);
    }
}

__device__ __forceinline__ void mma_block(
    float acc[2][8][4], uint32_t Af[2][2][4], uint32_t Bf[2][4][4])
{
    #pragma unroll
    for (int i = 0; i < 2; ++i)
        #pragma unroll
        for (int j = 0; j < 8; ++j) {
            const uint32_t bh0 = Bf[0][j >> 1][(j & 1) * 2];
            const uint32_t bh1 = Bf[0][j >> 1][(j & 1) * 2 + 1];
            const uint32_t bl0 = Bf[1][j >> 1][(j & 1) * 2];
            const uint32_t bl1 = Bf[1][j >> 1][(j & 1) * 2 + 1];
            hmma(acc[i][j], Af[0][i], bh0, bh1);   // hi*hi
            hmma(acc[i][j], Af[0][i], bl0, bl1);   // hi*lo
            hmma(acc[i][j], Af[1][i], bh0, bh1);   // lo*hi
        }
}

__global__ __launch_bounds__(256, 1) void k_gemm_mma()
{
    extern __shared__ char dsm[];
    const int z   = blockIdx.z;
    const int cnt = g_cnt[z];
    const int m0  = blockIdx.y * BM;
    if (m0 >= cnt) return;
    const int n0  = blockIdx.x * BN;
    const int tid  = threadIdx.x;
    const int wid  = tid >> 5;
    const int lane = tid & 31;
    const int warpM = wid & 3;
    const int warpN = wid >> 2;

    uint32_t sb = (smem_u32(dsm) + 127u) & ~127u;

    float acc[2][8][4];
    #pragma unroll
    for (int i = 0; i < 2; ++i)
        #pragma unroll
        for (int j = 0; j < 8; ++j)
            #pragma unroll
            for (int q = 0; q < 4; ++q) acc[i][j][q] = 0.f;

    load_stage(z, m0, n0, 0,  sb,            tid); cp_commit();
    load_stage(z, m0, n0, BK, sb + STAGE_SZ, tid); cp_commit();

    const int sub  = lane >> 3;
    const int lrow = lane & 7;
    const int a_row = warpM * 32 + (sub & 1) * 8 + lrow;
    const int a_kb  = (sub >> 1) * 16;
    const int b_row = warpN * 64 + (sub >> 1) * 8 + lrow;
    const int b_kb  = (sub & 1) * 16;

    uint32_t Af[2][2][2][4];   // [buf][split][mtile][4]
    uint32_t Bf[2][2][4][4];   // [buf][split][ntile][4]

    for (int kt = 0; kt < KT; ++kt) {
        if (kt >= KT - 1) cp_wait<0>(); else cp_wait<1>();
        __syncthreads();
        if (kt + 2 < KT) {
            load_stage(z, m0, n0, (kt + 2) * BK, sb + ((kt + 2) % NSTAGE) * STAGE_SZ, tid);
            cp_commit();
        }
        const uint32_t st = sb + (kt % NSTAGE) * STAGE_SZ;

        // s-step software pipeline: LDSM(s+1) issued before MMA(s)
        load_frags(Af[0], Bf[0], st, 0, a_row, a_kb, b_row, b_kb);
        #pragma unroll
        for (int s = 0; s < 4; ++s) {
            const int cur = s & 1;
            if (s < 3)
                load_frags(Af[cur ^ 1], Bf[cur ^ 1], st, (s + 1) * 32,
                           a_row, a_kb, b_row, b_kb);
            mma_block(acc, Af[cur], Bf[cur]);
        }
    }

    const int g = lane >> 2, tq = lane & 3;
    float* Lg = g_logits[z];
    #pragma unroll
    for (int i = 0; i < 2; ++i) {
        const int r0 = m0 + warpM * 32 + i * 16 + g;
        #pragma unroll
        for (int j = 0; j < 8; ++j) {
            const int col = n0 + warpN * 64 + j * 8 + 2 * tq;
            if (r0 < cnt)
                *reinterpret_cast<float2*>(Lg + (size_t)r0 * CDIM + col) =
                    make_float2(acc[i][j][0], acc[i][j][1]);
            if (r0 + 8 < cnt)
                *reinterpret_cast<float2*>(Lg + (size_t)(r0 + 8) * CDIM + col) =
                    make_float2(acc[i][j][2], acc[i][j][3]);
        }
    }
}

// ---------------------------------------------------------------------------
// Kernel 4: softmax + scale by non_end + scatter + log_prob.
// ---------------------------------------------------------------------------
__global__ __launch_bounds__(256) void k_softmax(
    const int* __restrict__ Y,
    const float* __restrict__ b_hcw, const float* __restrict__ b_roo,
    float* __restrict__ out)
{
    const int z    = blockIdx.z;
    const int warp = threadIdx.x >> 5;
    const int lane = threadIdx.x & 31;
    const int pos  = blockIdx.x * 8 + warp;
    if (pos >= g_cnt[z]) return;
    const int t = g_list[z][pos];

    const float* __restrict__ bias = (z == 0) ? b_hcw : b_roo;
    const float* Lrow = g_logits[z] + (size_t)pos * CDIM;
    const float4* L4 = reinterpret_cast<const float4*>(Lrow);
    const float4* B4 = reinterpret_cast<const float4*>(bias);

    float4 v[8];
    float mx = -1e30f;
    #pragma unroll
    for (int i = 0; i < 8; ++i) {
        float4 a = L4[lane + 32 * i];
        float4 b = B4[lane + 32 * i];
        a.x += b.x; a.y += b.y; a.z += b.z; a.w += b.w;
        v[i] = a;
        mx = fmaxf(mx, fmaxf(fmaxf(a.x, a.y), fmaxf(a.z, a.w)));
    }
    #pragma unroll
    for (int o = 16; o; o >>= 1) mx = fmaxf(mx, __shfl_xor_sync(0xffffffffu, mx, o));

    float sum = 0.f;
    #pragma unroll
    for (int i = 0; i < 8; ++i) {
        v[i].x = expf(v[i].x - mx); v[i].y = expf(v[i].y - mx);
        v[i].z = expf(v[i].z - mx); v[i].w = expf(v[i].w - mx);
        sum += (v[i].x + v[i].y) + (v[i].z + v[i].w);
    }
    #pragma unroll
    for (int o = 16; o; o >>= 1) sum += __shfl_xor_sync(0xffffffffu, sum, o);

    const float ne = g_nonend[t];
    const float scale = ne / sum;

    float* row = out + NTOK + (size_t)t * OUTW + ((z == 0) ? 2 : 2 + CDIM);
    #pragma unroll
    for (int i = 0; i < 8; ++i) {
        const int c0 = 4 * (lane + 32 * i);
        *reinterpret_cast<float2*>(row + c0)     = make_float2(v[i].x * scale, v[i].y * scale);
        *reinterpret_cast<float2*>(row + c0 + 2) = make_float2(v[i].z * scale, v[i].w * scale);
    }

    if (lane == 0) {
        const int yv = Y[t];
        int idx = yv - 2 - ((z == 0) ? 0 : CDIM);
        idx = min(max(idx, 0), CDIM - 1);
        const float li = Lrow[idx] + bias[idx];
        out[t] = (li - mx) - logf(sum) + logf(ne);
    }
}

// ---------------------------------------------------------------------------
// Launcher
// ---------------------------------------------------------------------------
extern "C" void kernel_launch(void* const* d_in, const int* in_sizes, int n_in,
                              void* d_out, int out_size)
{
    const float* X     = (const float*)d_in[0];
    const int*   pY    = (const int*)d_in[1];
    const int*   Y     = (const int*)d_in[2];
    const float* W_end = (const float*)d_in[3];
    const float* b_end = (const float*)d_in[4];
    const float* W_hcw = (const float*)d_in[5];
    const float* b_hcw = (const float*)d_in[6];
    const float* W_roo = (const float*)d_in[7];
    const float* b_roo = (const float*)d_in[8];
    float* out = (float*)d_out;
    (void)in_sizes; (void)n_in; (void)out_size;

    const int dyn = 128 + NSTAGE * STAGE_SZ;   // 196736
    static bool attr_set = false;
    if (!attr_set) {
        cudaFuncSetAttribute(k_gemm_mma, cudaFuncAttributeMaxDynamicSharedMemorySize, dyn);
        attr_set = true;
    }

    k_reset<<<1, 32>>>();
    k_classify<<<NTOK / 8, 256>>>(X, pY, W_end, b_end, out);
    k_padzero<<<dim3(16, 2), 256>>>();
    k_convert_w<<<dim3(2 * CDIM / 8, 2), 256>>>(W_hcw, W_roo);
    k_gemm_mma<<<dim3(CDIM / BN, NTOK / BM, 2), 256, dyn>>>();
    k_softmax<<<dim3(NTOK / 8, 1, 2), 256>>>(Y, b_hcw, b_roo, out);
}